// round 4
// baseline (speedup 1.0000x reference)
#include <cuda_runtime.h>

// MemoryModule: B=8,L=12,T=36,D=1024,F=3,C=32
//   mq[c,t] = sum_{f,g} Wm[c,f] Wq[c,g] G[t,f,g] + bm[c]*(Wq[c]·XLsum)
//           + bq[c]*(Wm[c]·XHsum[t]) + D*bm[c]*bq[c]
//   o[c,d]  = sum_f Wc[c,f] * (sum_t att[c,t]*xh[t,d,f]) + bc[c]
// v4: k_gram pure-LDG streaming (no smem), k_out 64-reg / 2-stage pipeline.

#define Bb 8
#define Ll 12
#define Tt 36
#define Dd 1024
#define Ff 3
#define Cc 32
#define BL (Bb * Ll)
#define DF (Dd * Ff)        // 3072
#define DC 64
#define CHUNKS (Dd / DC)    // 16

__device__ __align__(16) float g_att2[BL * Tt * Cc * 2]; // (a,a) pairs, [bl][t][c]
__device__ float g_G[BL * Tt * 12];                       // G[9] + XHsum[3]

#define FFMA2(d, a, b) \
    asm("fma.rn.f32x2 %0, %1, %2, %0;" : "+l"(d) : "l"(a), "l"(b))

#define CP16(dst, src) \
    asm volatile("cp.async.cg.shared.global [%0], [%1], 16;" :: "r"(dst), "l"(src))

union U2F { unsigned long long u; float2 f; };

// ---------------------------------------------------------------------------
// k_gram: warp = one (bl, t). Lane owns 4 consecutive d's -> 3 LDG.128 for xh
// and 3 for xl per 128-d sweep. No smem, no syncthreads. Grid (3,96) x 384.
// ---------------------------------------------------------------------------
__global__ __launch_bounds__(384) void k_gram(
    const float* __restrict__ xh_g, const float* __restrict__ xl_g)
{
    int tg = blockIdx.x, bl = blockIdx.y;
    int w = threadIdx.x >> 5, lane = threadIdx.x & 31;
    int t = tg * 12 + w;

    const float4* xp = (const float4*)(xh_g + ((size_t)bl * Tt + t) * DF);
    const float4* lp = (const float4*)(xl_g + (size_t)bl * DF);

    float V[12];
    #pragma unroll
    for (int j = 0; j < 12; j++) V[j] = 0.0f;
    // V[0..8] = G[3x3] (row = xh feature, col = xl feature), V[9..11] = XHsum

    #pragma unroll 4
    for (int it = 0; it < 8; it++) {
        int qi = it * 96 + lane * 3;        // float4 index of lane's 4-d quad
        float4 v0 = xp[qi], v1 = xp[qi + 1], v2 = xp[qi + 2];
        float4 u0 = lp[qi], u1 = lp[qi + 1], u2 = lp[qi + 2];

        // d0: a=(v0.x,v0.y,v0.z) b=(u0.x,u0.y,u0.z)
        V[0] = fmaf(v0.x, u0.x, V[0]); V[1] = fmaf(v0.x, u0.y, V[1]); V[2] = fmaf(v0.x, u0.z, V[2]);
        V[3] = fmaf(v0.y, u0.x, V[3]); V[4] = fmaf(v0.y, u0.y, V[4]); V[5] = fmaf(v0.y, u0.z, V[5]);
        V[6] = fmaf(v0.z, u0.x, V[6]); V[7] = fmaf(v0.z, u0.y, V[7]); V[8] = fmaf(v0.z, u0.z, V[8]);
        V[9] += v0.x; V[10] += v0.y; V[11] += v0.z;
        // d1: a=(v0.w,v1.x,v1.y) b=(u0.w,u1.x,u1.y)
        V[0] = fmaf(v0.w, u0.w, V[0]); V[1] = fmaf(v0.w, u1.x, V[1]); V[2] = fmaf(v0.w, u1.y, V[2]);
        V[3] = fmaf(v1.x, u0.w, V[3]); V[4] = fmaf(v1.x, u1.x, V[4]); V[5] = fmaf(v1.x, u1.y, V[5]);
        V[6] = fmaf(v1.y, u0.w, V[6]); V[7] = fmaf(v1.y, u1.x, V[7]); V[8] = fmaf(v1.y, u1.y, V[8]);
        V[9] += v0.w; V[10] += v1.x; V[11] += v1.y;
        // d2: a=(v1.z,v1.w,v2.x) b=(u1.z,u1.w,u2.x)
        V[0] = fmaf(v1.z, u1.z, V[0]); V[1] = fmaf(v1.z, u1.w, V[1]); V[2] = fmaf(v1.z, u2.x, V[2]);
        V[3] = fmaf(v1.w, u1.z, V[3]); V[4] = fmaf(v1.w, u1.w, V[4]); V[5] = fmaf(v1.w, u2.x, V[5]);
        V[6] = fmaf(v2.x, u1.z, V[6]); V[7] = fmaf(v2.x, u1.w, V[7]); V[8] = fmaf(v2.x, u2.x, V[8]);
        V[9] += v1.z; V[10] += v1.w; V[11] += v2.x;
        // d3: a=(v2.y,v2.z,v2.w) b=(u2.y,u2.z,u2.w)
        V[0] = fmaf(v2.y, u2.y, V[0]); V[1] = fmaf(v2.y, u2.z, V[1]); V[2] = fmaf(v2.y, u2.w, V[2]);
        V[3] = fmaf(v2.z, u2.y, V[3]); V[4] = fmaf(v2.z, u2.z, V[4]); V[5] = fmaf(v2.z, u2.w, V[5]);
        V[6] = fmaf(v2.w, u2.y, V[6]); V[7] = fmaf(v2.w, u2.z, V[7]); V[8] = fmaf(v2.w, u2.w, V[8]);
        V[9] += v2.y; V[10] += v2.z; V[11] += v2.w;
    }

    #pragma unroll
    for (int j = 0; j < 12; j++) {
        #pragma unroll
        for (int o = 16; o; o >>= 1) V[j] += __shfl_down_sync(~0u, V[j], o);
    }
    if (lane == 0) {
        float* gp = g_G + ((size_t)bl * Tt + t) * 12;
        #pragma unroll
        for (int j = 0; j < 12; j++) gp[j] = V[j];
    }
}

// ---------------------------------------------------------------------------
// k_score: per bl: XLsum + scores + softmax -> g_att2. Grid 96 x 256.
// ---------------------------------------------------------------------------
__global__ __launch_bounds__(256) void k_score(
    const float* __restrict__ xl_g,
    const float* __restrict__ Wq, const float* __restrict__ bq,
    const float* __restrict__ Wm, const float* __restrict__ bm)
{
    __shared__ float s_G[Tt][12];
    __shared__ float s_mq[Cc][Tt];
    __shared__ float s_XL[3];

    int bl = blockIdx.x;
    int tid = threadIdx.x, w = tid >> 5, lane = tid & 31;

    if (tid < 3) s_XL[tid] = 0.0f;
    for (int i = tid; i < Tt * 12; i += 256)
        ((float*)s_G)[i] = g_G[(size_t)bl * Tt * 12 + i];

    {
        const float* xl = xl_g + (size_t)bl * DF;
        float x0 = 0, x1 = 0, x2 = 0;
        for (int d = tid; d < Dd; d += 256) {
            x0 += xl[d * 3 + 0]; x1 += xl[d * 3 + 1]; x2 += xl[d * 3 + 2];
        }
        #pragma unroll
        for (int o = 16; o; o >>= 1) {
            x0 += __shfl_down_sync(~0u, x0, o);
            x1 += __shfl_down_sync(~0u, x1, o);
            x2 += __shfl_down_sync(~0u, x2, o);
        }
        __syncthreads();
        if (lane == 0) {
            atomicAdd(&s_XL[0], x0); atomicAdd(&s_XL[1], x1); atomicAdd(&s_XL[2], x2);
        }
    }
    __syncthreads();

    for (int i = tid; i < Cc * Tt; i += 256) {
        int c = i / Tt, t = i - c * Tt;
        float wm0 = Wm[c * 3 + 0], wm1 = Wm[c * 3 + 1], wm2 = Wm[c * 3 + 2];
        float wq0 = Wq[c * 3 + 0], wq1 = Wq[c * 3 + 1], wq2 = Wq[c * 3 + 2];
        float bmc = bm[c], bqc = bq[c];
        const float* Gp = s_G[t];
        float v = wm0 * (wq0 * Gp[0] + wq1 * Gp[1] + wq2 * Gp[2])
                + wm1 * (wq0 * Gp[3] + wq1 * Gp[4] + wq2 * Gp[5])
                + wm2 * (wq0 * Gp[6] + wq1 * Gp[7] + wq2 * Gp[8])
                + bmc * (wq0 * s_XL[0] + wq1 * s_XL[1] + wq2 * s_XL[2])
                + bqc * (wm0 * Gp[9] + wm1 * Gp[10] + wm2 * Gp[11])
                + (float)Dd * bmc * bqc;
        s_mq[c][t] = fmaxf(v, 0.0f);
    }
    __syncthreads();

    #pragma unroll
    for (int k = 0; k < 4; k++) {
        int c = w + 8 * k;
        float v0 = s_mq[c][lane];
        float v1 = (lane < Tt - 32) ? s_mq[c][lane + 32] : -3.0e38f;
        float mx = fmaxf(v0, v1);
        #pragma unroll
        for (int o = 16; o; o >>= 1) mx = fmaxf(mx, __shfl_xor_sync(~0u, mx, o));
        float e0 = __expf(v0 - mx);
        float e1 = (lane < Tt - 32) ? __expf(v1 - mx) : 0.0f;
        float s = e0 + e1;
        #pragma unroll
        for (int o = 16; o; o >>= 1) s += __shfl_xor_sync(~0u, s, o);
        float inv = 1.0f / s;
        float2* ap = (float2*)g_att2 + (size_t)bl * Tt * Cc;
        float a0 = e0 * inv;
        ap[lane * Cc + c] = make_float2(a0, a0);
        if (lane < Tt - 32) {
            float a1 = e1 * inv;
            ap[(lane + 32) * Cc + c] = make_float2(a1, a1);
        }
    }
}

// ---------------------------------------------------------------------------
// k_out: CTA = (bl, 64-d chunk). 64-reg cap -> 4 CTAs/SM. 2-stage cp.async
// pipeline. Lane = channel, warp covers 8 d, FFMA2 accumulation.
// ---------------------------------------------------------------------------
#define SM_TILE_F (Tt * DC * Ff)          // 6912 floats
#define SM_ATT_F  (Tt * Cc * 2)           // 2304 floats
#define SM_XL_F   (DC * Ff)               // 192 floats
#define ROW_CP    (DC * Ff / 4)           // 48 cp16 per t-row
#define T_SPLIT   12                      // rows in stage A

__global__ __launch_bounds__(256, 4) void k_out(
    const float* __restrict__ xl_g, const float* __restrict__ xh_g,
    const float* __restrict__ Wq, const float* __restrict__ bq,
    const float* __restrict__ Wc, const float* __restrict__ bc,
    float* __restrict__ out)
{
    extern __shared__ float sm[];
    float* s_tile = sm;
    float* s_att  = sm + SM_TILE_F;
    float* s_xl   = sm + SM_TILE_F + SM_ATT_F;

    int blk = blockIdx.x;
    int bl = blk / CHUNKS, chunk = blk - bl * CHUNKS;
    int b = bl / Ll, l = bl - b * Ll;
    int tid = threadIdx.x;

    const float* xh_bl   = xh_g + (size_t)bl * Tt * DF + chunk * DC * Ff;
    const float* att_src = (const float*)g_att2 + (size_t)bl * Tt * Cc * 2;
    const float* xl_src  = xl_g + (size_t)bl * DF + chunk * DC * Ff;

    // ---- stage A: att + xl + tile rows [0,12) ----
    for (int i = tid; i < SM_ATT_F / 4; i += 256)
        CP16((unsigned)__cvta_generic_to_shared(s_att + i * 4), att_src + i * 4);
    if (tid < SM_XL_F / 4)
        CP16((unsigned)__cvta_generic_to_shared(s_xl + tid * 4), xl_src + tid * 4);
    for (int i = tid; i < T_SPLIT * ROW_CP; i += 256) {
        int row = i / ROW_CP, col = (i - row * ROW_CP) * 4;
        CP16((unsigned)__cvta_generic_to_shared(s_tile + row * (DC * Ff) + col),
             xh_bl + (size_t)row * DF + col);
    }
    asm volatile("cp.async.commit_group;");

    // ---- stage B: tile rows [12,36) ----
    for (int i = tid; i < (Tt - T_SPLIT) * ROW_CP; i += 256) {
        int row = T_SPLIT + i / ROW_CP, col = (i % ROW_CP) * 4;
        CP16((unsigned)__cvta_generic_to_shared(s_tile + row * (DC * Ff) + col),
             xh_bl + (size_t)row * DF + col);
    }
    asm volatile("cp.async.commit_group;");

    int wid = tid >> 5, c = tid & 31;
    int dw = wid * 8;

    unsigned long long H[12];
    #pragma unroll
    for (int k = 0; k < 12; k++) H[k] = 0ull;

    const unsigned long long* ap = (const unsigned long long*)s_att + c;
    const float* tp = s_tile + dw * Ff;

    asm volatile("cp.async.wait_group 1;");
    __syncthreads();

    #pragma unroll 3
    for (int t = 0; t < T_SPLIT; t++) {
        unsigned long long av = ap[t * Cc];
        const ulonglong2* p = (const ulonglong2*)(tp + t * (DC * Ff));
        #pragma unroll
        for (int g = 0; g < 2; g++) {
            ulonglong2 x0 = p[3 * g + 0];
            ulonglong2 x1 = p[3 * g + 1];
            ulonglong2 x2 = p[3 * g + 2];
            FFMA2(H[6 * g + 0], x0.x, av);
            FFMA2(H[6 * g + 1], x0.y, av);
            FFMA2(H[6 * g + 2], x1.x, av);
            FFMA2(H[6 * g + 3], x1.y, av);
            FFMA2(H[6 * g + 4], x2.x, av);
            FFMA2(H[6 * g + 5], x2.y, av);
        }
    }

    asm volatile("cp.async.wait_group 0;");
    __syncthreads();

    #pragma unroll 3
    for (int t = T_SPLIT; t < Tt; t++) {
        unsigned long long av = ap[t * Cc];
        const ulonglong2* p = (const ulonglong2*)(tp + t * (DC * Ff));
        #pragma unroll
        for (int g = 0; g < 2; g++) {
            ulonglong2 x0 = p[3 * g + 0];
            ulonglong2 x1 = p[3 * g + 1];
            ulonglong2 x2 = p[3 * g + 2];
            FFMA2(H[6 * g + 0], x0.x, av);
            FFMA2(H[6 * g + 1], x0.y, av);
            FFMA2(H[6 * g + 2], x1.x, av);
            FFMA2(H[6 * g + 3], x1.y, av);
            FFMA2(H[6 * g + 4], x2.x, av);
            FFMA2(H[6 * g + 5], x2.y, av);
        }
    }

    float wc0 = Wc[c * 3 + 0], wc1 = Wc[c * 3 + 1], wc2 = Wc[c * 3 + 2], bcc = bc[c];
    float wq0 = Wq[c * 3 + 0], wq1 = Wq[c * 3 + 1], wq2 = Wq[c * 3 + 2], bqc = bq[c];

    float* op = out + (((size_t)b * Cc + c) * Ll + l) * Dd + chunk * DC + dw;

    #pragma unroll
    for (int g = 0; g < 2; g++) {
        U2F k0, k1, k2, k3, k4, k5;
        k0.u = H[6 * g + 0]; k1.u = H[6 * g + 1]; k2.u = H[6 * g + 2];
        k3.u = H[6 * g + 3]; k4.u = H[6 * g + 4]; k5.u = H[6 * g + 5];
        // pair layout: (d0f0,d0f1)(d0f2,d1f0)(d1f1,d1f2)(d2f0,d2f1)(d2f2,d3f0)(d3f1,d3f2)
        float ov0 = fmaf(wc2, k1.f.x, fmaf(wc1, k0.f.y, fmaf(wc0, k0.f.x, bcc)));
        float ov1 = fmaf(wc2, k2.f.y, fmaf(wc1, k2.f.x, fmaf(wc0, k1.f.y, bcc)));
        float ov2 = fmaf(wc2, k4.f.x, fmaf(wc1, k3.f.y, fmaf(wc0, k3.f.x, bcc)));
        float ov3 = fmaf(wc2, k5.f.y, fmaf(wc1, k5.f.x, fmaf(wc0, k4.f.y, bcc)));

        const float* xp = s_xl + (dw + 4 * g) * Ff;
        float q0 = fmaf(wq2, xp[2],  fmaf(wq1, xp[1],  fmaf(wq0, xp[0], bqc)));
        float q1 = fmaf(wq2, xp[5],  fmaf(wq1, xp[4],  fmaf(wq0, xp[3], bqc)));
        float q2 = fmaf(wq2, xp[8],  fmaf(wq1, xp[7],  fmaf(wq0, xp[6], bqc)));
        float q3 = fmaf(wq2, xp[11], fmaf(wq1, xp[10], fmaf(wq0, xp[9], bqc)));

        float4 res = make_float4(q0 + ov0, q1 + ov1, q2 + ov2, q3 + ov3);
        *(float4*)(op + 4 * g) = res;
    }
}

extern "C" void kernel_launch(void* const* d_in, const int* in_sizes, int n_in,
                              void* d_out, int out_size)
{
    const float* xl = (const float*)d_in[0];
    const float* xh = (const float*)d_in[1];
    const float* Wq = (const float*)d_in[2];
    const float* bq = (const float*)d_in[3];
    const float* Wm = (const float*)d_in[4];
    const float* bm = (const float*)d_in[5];
    const float* Wc = (const float*)d_in[6];
    const float* bc = (const float*)d_in[7];
    float* out = (float*)d_out;

    static int attr_set = 0;
    if (!attr_set) {
        cudaFuncSetAttribute(k_out, cudaFuncAttributeMaxDynamicSharedMemorySize,
                             (SM_TILE_F + SM_ATT_F + SM_XL_F) * 4);
        attr_set = 1;
    }

    k_gram<<<dim3(3, BL), 384>>>(xh, xl);
    k_score<<<BL, 256>>>(xl, Wq, bq, Wm, bm);
    k_out<<<BL * CHUNKS, 256, (SM_TILE_F + SM_ATT_F + SM_XL_F) * 4>>>(
        xl, xh, Wq, bq, Wc, bc, out);
}

// round 5
// speedup vs baseline: 1.2800x; 1.2800x over previous
#include <cuda_runtime.h>

// MemoryModule: B=8,L=12,T=36,D=1024,F=3,C=32
//   mq[c,t] = sum_{f,g} Wm[c,f] Wq[c,g] G[t,f,g] + bm[c]*(Wq[c]·XLsum)
//           + bq[c]*(Wm[c]·XHsum[t]) + D*bm[c]*bq[c]
//   o[c,d]  = sum_f Wc[c,f] * (sum_t att[c,t]*xh[t,d,f]) + bc[c]
// v5: k_out register-blocked 8 channels/lane (kills smem broadcast wall),
//     k_gram d-split x2 for occupancy, att stored plain f32 [bl][t][c].

#define Bb 8
#define Ll 12
#define Tt 36
#define Dd 1024
#define Ff 3
#define Cc 32
#define BL (Bb * Ll)
#define DF (Dd * Ff)        // 3072
#define DC 128
#define CHUNKS (Dd / DC)    // 8

__device__ __align__(16) float g_attf[BL * Tt * Cc];   // f32 att, [bl][t][c]
__device__ float g_G[2 * BL * Tt * 12];                 // 2 d-halves of G[9]+XHsum[3]

#define FFMA2(d, a, b) \
    asm("fma.rn.f32x2 %0, %1, %2, %0;" : "+l"(d) : "l"(a), "l"(b))

#define CP16(dst, src) \
    asm volatile("cp.async.cg.shared.global [%0], [%1], 16;" :: "r"(dst), "l"(src))

union U2F { unsigned long long u; float2 f; };

// ---------------------------------------------------------------------------
// k_gram: warp = one (bl, t, d-half of 512). Lane owns 4 consecutive d's:
// 3 LDG.128 xh + 3 LDG.128 xl per 128-d sweep. Grid (24,96) x 96 threads.
// blockIdx.x: 0..11 -> t-group (half 0), 12..23 -> t-group (half 1).
// ---------------------------------------------------------------------------
__global__ __launch_bounds__(96) void k_gram(
    const float* __restrict__ xh_g, const float* __restrict__ xl_g)
{
    int bx = blockIdx.x, bl = blockIdx.y;
    int w = threadIdx.x >> 5, lane = threadIdx.x & 31;
    int dh = bx >= 12;
    int t = (bx - dh * 12) * 3 + w;

    const float4* xp = (const float4*)(xh_g + ((size_t)bl * Tt + t) * DF) + dh * 384;
    const float4* lp = (const float4*)(xl_g + (size_t)bl * DF) + dh * 384;

    float V[12];
    #pragma unroll
    for (int j = 0; j < 12; j++) V[j] = 0.0f;

    #pragma unroll 4
    for (int it = 0; it < 4; it++) {
        int qi = it * 96 + lane * 3;
        float4 v0 = xp[qi], v1 = xp[qi + 1], v2 = xp[qi + 2];
        float4 u0 = lp[qi], u1 = lp[qi + 1], u2 = lp[qi + 2];

        V[0] = fmaf(v0.x, u0.x, V[0]); V[1] = fmaf(v0.x, u0.y, V[1]); V[2] = fmaf(v0.x, u0.z, V[2]);
        V[3] = fmaf(v0.y, u0.x, V[3]); V[4] = fmaf(v0.y, u0.y, V[4]); V[5] = fmaf(v0.y, u0.z, V[5]);
        V[6] = fmaf(v0.z, u0.x, V[6]); V[7] = fmaf(v0.z, u0.y, V[7]); V[8] = fmaf(v0.z, u0.z, V[8]);
        V[9] += v0.x; V[10] += v0.y; V[11] += v0.z;

        V[0] = fmaf(v0.w, u0.w, V[0]); V[1] = fmaf(v0.w, u1.x, V[1]); V[2] = fmaf(v0.w, u1.y, V[2]);
        V[3] = fmaf(v1.x, u0.w, V[3]); V[4] = fmaf(v1.x, u1.x, V[4]); V[5] = fmaf(v1.x, u1.y, V[5]);
        V[6] = fmaf(v1.y, u0.w, V[6]); V[7] = fmaf(v1.y, u1.x, V[7]); V[8] = fmaf(v1.y, u1.y, V[8]);
        V[9] += v0.w; V[10] += v1.x; V[11] += v1.y;

        V[0] = fmaf(v1.z, u1.z, V[0]); V[1] = fmaf(v1.z, u1.w, V[1]); V[2] = fmaf(v1.z, u2.x, V[2]);
        V[3] = fmaf(v1.w, u1.z, V[3]); V[4] = fmaf(v1.w, u1.w, V[4]); V[5] = fmaf(v1.w, u2.x, V[5]);
        V[6] = fmaf(v2.x, u1.z, V[6]); V[7] = fmaf(v2.x, u1.w, V[7]); V[8] = fmaf(v2.x, u2.x, V[8]);
        V[9] += v1.z; V[10] += v1.w; V[11] += v2.x;

        V[0] = fmaf(v2.y, u2.y, V[0]); V[1] = fmaf(v2.y, u2.z, V[1]); V[2] = fmaf(v2.y, u2.w, V[2]);
        V[3] = fmaf(v2.z, u2.y, V[3]); V[4] = fmaf(v2.z, u2.z, V[4]); V[5] = fmaf(v2.z, u2.w, V[5]);
        V[6] = fmaf(v2.w, u2.y, V[6]); V[7] = fmaf(v2.w, u2.z, V[7]); V[8] = fmaf(v2.w, u2.w, V[8]);
        V[9] += v2.y; V[10] += v2.z; V[11] += v2.w;
    }

    #pragma unroll
    for (int j = 0; j < 12; j++) {
        #pragma unroll
        for (int o = 16; o; o >>= 1) V[j] += __shfl_down_sync(~0u, V[j], o);
    }
    if (lane == 0) {
        float* gp = g_G + (((size_t)dh * BL + bl) * Tt + t) * 12;
        #pragma unroll
        for (int j = 0; j < 12; j++) gp[j] = V[j];
    }
}

// ---------------------------------------------------------------------------
// k_score: per bl: sum G halves + XLsum + scores + softmax -> g_attf.
// ---------------------------------------------------------------------------
__global__ __launch_bounds__(256) void k_score(
    const float* __restrict__ xl_g,
    const float* __restrict__ Wq, const float* __restrict__ bq,
    const float* __restrict__ Wm, const float* __restrict__ bm)
{
    __shared__ float s_G[Tt][12];
    __shared__ float s_mq[Cc][Tt];
    __shared__ float s_XL[3];

    int bl = blockIdx.x;
    int tid = threadIdx.x, w = tid >> 5, lane = tid & 31;

    if (tid < 3) s_XL[tid] = 0.0f;
    for (int i = tid; i < Tt * 12; i += 256)
        ((float*)s_G)[i] = g_G[(size_t)bl * Tt * 12 + i]
                         + g_G[((size_t)BL + bl) * Tt * 12 + i];

    {
        const float* xl = xl_g + (size_t)bl * DF;
        float x0 = 0, x1 = 0, x2 = 0;
        for (int d = tid; d < Dd; d += 256) {
            x0 += xl[d * 3 + 0]; x1 += xl[d * 3 + 1]; x2 += xl[d * 3 + 2];
        }
        #pragma unroll
        for (int o = 16; o; o >>= 1) {
            x0 += __shfl_down_sync(~0u, x0, o);
            x1 += __shfl_down_sync(~0u, x1, o);
            x2 += __shfl_down_sync(~0u, x2, o);
        }
        __syncthreads();
        if (lane == 0) {
            atomicAdd(&s_XL[0], x0); atomicAdd(&s_XL[1], x1); atomicAdd(&s_XL[2], x2);
        }
    }
    __syncthreads();

    for (int i = tid; i < Cc * Tt; i += 256) {
        int c = i / Tt, t = i - c * Tt;
        float wm0 = Wm[c * 3 + 0], wm1 = Wm[c * 3 + 1], wm2 = Wm[c * 3 + 2];
        float wq0 = Wq[c * 3 + 0], wq1 = Wq[c * 3 + 1], wq2 = Wq[c * 3 + 2];
        float bmc = bm[c], bqc = bq[c];
        const float* Gp = s_G[t];
        float v = wm0 * (wq0 * Gp[0] + wq1 * Gp[1] + wq2 * Gp[2])
                + wm1 * (wq0 * Gp[3] + wq1 * Gp[4] + wq2 * Gp[5])
                + wm2 * (wq0 * Gp[6] + wq1 * Gp[7] + wq2 * Gp[8])
                + bmc * (wq0 * s_XL[0] + wq1 * s_XL[1] + wq2 * s_XL[2])
                + bqc * (wm0 * Gp[9] + wm1 * Gp[10] + wm2 * Gp[11])
                + (float)Dd * bmc * bqc;
        s_mq[c][t] = fmaxf(v, 0.0f);
    }
    __syncthreads();

    #pragma unroll
    for (int k = 0; k < 4; k++) {
        int c = w + 8 * k;
        float v0 = s_mq[c][lane];
        float v1 = (lane < Tt - 32) ? s_mq[c][lane + 32] : -3.0e38f;
        float mx = fmaxf(v0, v1);
        #pragma unroll
        for (int o = 16; o; o >>= 1) mx = fmaxf(mx, __shfl_xor_sync(~0u, mx, o));
        float e0 = __expf(v0 - mx);
        float e1 = (lane < Tt - 32) ? __expf(v1 - mx) : 0.0f;
        float s = e0 + e1;
        #pragma unroll
        for (int o = 16; o; o >>= 1) s += __shfl_xor_sync(~0u, s, o);
        float inv = 1.0f / s;
        float* ap = g_attf + (size_t)bl * Tt * Cc;
        ap[lane * Cc + c] = e0 * inv;
        if (lane < Tt - 32) ap[(lane + 32) * Cc + c] = e1 * inv;
    }
}

// ---------------------------------------------------------------------------
// k_out: CTA = (bl, 128-d chunk). Lane = (cg = lane>>3, dp = lane&7):
// 8 channels x 1 d-pair per lane, 24 FFMA2 accumulators. Crossbar traffic:
// 2 LDS.128 (att) + 3 LDS.64 (xh) per (warp, t) for 24 FFMA2.
// Grid 768 x 256, smem 60KB, 3 CTAs/SM.
// ---------------------------------------------------------------------------
#define SM_TILE_F (Tt * DC * Ff)   // 13824
#define SM_ATT_F  (Tt * Cc)        // 1152
#define SM_XL_F   (DC * Ff)        // 384
#define ROW_CP    (DC * Ff / 4)    // 96
#define T_SPLIT   12

__global__ __launch_bounds__(256, 3) void k_out(
    const float* __restrict__ xl_g, const float* __restrict__ xh_g,
    const float* __restrict__ Wq, const float* __restrict__ bq,
    const float* __restrict__ Wc, const float* __restrict__ bc,
    float* __restrict__ out)
{
    extern __shared__ float sm[];
    float* s_tile = sm;
    float* s_att  = sm + SM_TILE_F;
    float* s_xl   = sm + SM_TILE_F + SM_ATT_F;

    int blk = blockIdx.x;
    int bl = blk / CHUNKS, chunk = blk - bl * CHUNKS;
    int b = bl / Ll, l = bl - b * Ll;
    int tid = threadIdx.x;

    const float* xh_bl   = xh_g + (size_t)bl * Tt * DF + chunk * DC * Ff;
    const float* att_src = g_attf + (size_t)bl * Tt * Cc;
    const float* xl_src  = xl_g + (size_t)bl * DF + chunk * DC * Ff;

    // stage A: att + xl + tile rows [0,12)
    for (int i = tid; i < SM_ATT_F / 4; i += 256)
        CP16((unsigned)__cvta_generic_to_shared(s_att + i * 4), att_src + i * 4);
    if (tid < SM_XL_F / 4)
        CP16((unsigned)__cvta_generic_to_shared(s_xl + tid * 4), xl_src + tid * 4);
    for (int i = tid; i < T_SPLIT * ROW_CP; i += 256) {
        int row = i / ROW_CP, col = (i - row * ROW_CP) * 4;
        CP16((unsigned)__cvta_generic_to_shared(s_tile + row * (DC * Ff) + col),
             xh_bl + (size_t)row * DF + col);
    }
    asm volatile("cp.async.commit_group;");

    // stage B: tile rows [12,36)
    for (int i = tid; i < (Tt - T_SPLIT) * ROW_CP; i += 256) {
        int row = T_SPLIT + i / ROW_CP, col = (i % ROW_CP) * 4;
        CP16((unsigned)__cvta_generic_to_shared(s_tile + row * (DC * Ff) + col),
             xh_bl + (size_t)row * DF + col);
    }
    asm volatile("cp.async.commit_group;");

    int wid = tid >> 5, lane = tid & 31;
    int cg = lane >> 3, dp = lane & 7;
    int dloc = wid * 16 + dp * 2;          // lane's first local d (even)

    unsigned long long A[24];
    #pragma unroll
    for (int k = 0; k < 24; k++) A[k] = 0ull;

    const float* ab = s_att + cg * 8;                 // + t*32
    const unsigned long long* tb =
        (const unsigned long long*)(s_tile + dloc * Ff); // + t*192 (u64 units)

    asm volatile("cp.async.wait_group 1;");
    __syncthreads();

    #pragma unroll 2
    for (int t = 0; t < T_SPLIT; t++) {
        float4 a0 = *(const float4*)(ab + t * Cc);
        float4 a1 = *(const float4*)(ab + t * Cc + 4);
        unsigned long long x0 = tb[t * 192 + 0];
        unsigned long long x1 = tb[t * 192 + 1];
        unsigned long long x2 = tb[t * 192 + 2];
        float av[8] = {a0.x, a0.y, a0.z, a0.w, a1.x, a1.y, a1.z, a1.w};
        #pragma unroll
        for (int k = 0; k < 8; k++) {
            U2F aa; aa.f = make_float2(av[k], av[k]);
            FFMA2(A[3 * k + 0], x0, aa.u);
            FFMA2(A[3 * k + 1], x1, aa.u);
            FFMA2(A[3 * k + 2], x2, aa.u);
        }
    }

    asm volatile("cp.async.wait_group 0;");
    __syncthreads();

    #pragma unroll 2
    for (int t = T_SPLIT; t < Tt; t++) {
        float4 a0 = *(const float4*)(ab + t * Cc);
        float4 a1 = *(const float4*)(ab + t * Cc + 4);
        unsigned long long x0 = tb[t * 192 + 0];
        unsigned long long x1 = tb[t * 192 + 1];
        unsigned long long x2 = tb[t * 192 + 2];
        float av[8] = {a0.x, a0.y, a0.z, a0.w, a1.x, a1.y, a1.z, a1.w};
        #pragma unroll
        for (int k = 0; k < 8; k++) {
            U2F aa; aa.f = make_float2(av[k], av[k]);
            FFMA2(A[3 * k + 0], x0, aa.u);
            FFMA2(A[3 * k + 1], x1, aa.u);
            FFMA2(A[3 * k + 2], x2, aa.u);
        }
    }

    // epilogue: q + Wc·H + bc, 2 d's per channel, 8 channels per lane
    int dglob = chunk * DC + dloc;
    const float* xp = s_xl + dloc * Ff;
    float x00 = xp[0], x01 = xp[1], x02 = xp[2];
    float x10 = xp[3], x11 = xp[4], x12 = xp[5];

    #pragma unroll
    for (int k = 0; k < 8; k++) {
        int c = cg * 8 + k;
        float wc0 = Wc[c * 3 + 0], wc1 = Wc[c * 3 + 1], wc2 = Wc[c * 3 + 2];
        float wq0 = Wq[c * 3 + 0], wq1 = Wq[c * 3 + 1], wq2 = Wq[c * 3 + 2];
        float bcc = bc[c], bqc = bq[c];

        U2F p0, p1, p2;
        p0.u = A[3 * k + 0]; p1.u = A[3 * k + 1]; p2.u = A[3 * k + 2];
        // pairs: p0=(d0f0,d0f1) p1=(d0f2,d1f0) p2=(d1f1,d1f2)
        float o0 = fmaf(wc2, p1.f.x, fmaf(wc1, p0.f.y, fmaf(wc0, p0.f.x, bcc)));
        float o1 = fmaf(wc2, p2.f.y, fmaf(wc1, p2.f.x, fmaf(wc0, p1.f.y, bcc)));
        float q0 = fmaf(wq2, x02, fmaf(wq1, x01, fmaf(wq0, x00, bqc)));
        float q1 = fmaf(wq2, x12, fmaf(wq1, x11, fmaf(wq0, x10, bqc)));

        float2 res = make_float2(q0 + o0, q1 + o1);
        *(float2*)(out + (((size_t)b * Cc + c) * Ll + l) * Dd + dglob) = res;
    }
}

extern "C" void kernel_launch(void* const* d_in, const int* in_sizes, int n_in,
                              void* d_out, int out_size)
{
    const float* xl = (const float*)d_in[0];
    const float* xh = (const float*)d_in[1];
    const float* Wq = (const float*)d_in[2];
    const float* bq = (const float*)d_in[3];
    const float* Wm = (const float*)d_in[4];
    const float* bm = (const float*)d_in[5];
    const float* Wc = (const float*)d_in[6];
    const float* bc = (const float*)d_in[7];
    float* out = (float*)d_out;

    static int attr_set = 0;
    if (!attr_set) {
        cudaFuncSetAttribute(k_out, cudaFuncAttributeMaxDynamicSharedMemorySize,
                             (SM_TILE_F + SM_ATT_F + SM_XL_F) * 4);
        attr_set = 1;
    }

    k_gram<<<dim3(24, BL), 96>>>(xh, xl);
    k_score<<<BL, 256>>>(xl, Wq, bq, Wm, bm);
    k_out<<<BL * CHUNKS, 256, (SM_TILE_F + SM_ATT_F + SM_XL_F) * 4>>>(
        xl, xh, Wq, bq, Wc, bc, out);
}